// round 2
// baseline (speedup 1.0000x reference)
#include <cuda_runtime.h>
#include <cstdint>

#define NN   100000
#define FIN  1024
#define HH   8
#define DD   16
#define CC   128
#define EE   600000
#define PP   3
#define OUTC 3
#define NEG  0.2f

// ---------------- scratch (static device globals; no allocs) ----------------
__device__ float g_h[(size_t)NN * CC];          // projected features [N,C]
__device__ float g_outs[(size_t)PP * NN * CC];  // per-metapath GAT outputs
__device__ float g_tmp[(size_t)PP * NN * CC];   // semantic GEMM output
__device__ float g_p[(size_t)EE * HH];          // per-edge exp(e) values
__device__ float g_als[(size_t)NN * HH];        // alpha_src logits per node
__device__ float g_ald[(size_t)NN * HH];        // alpha_dst logits per node
__device__ float g_denom[(size_t)PP * NN * HH]; // softmax denominators
__device__ float g_w[PP * CC];                  // semantic attn accumulators
__device__ float g_beta[PP];                    // semantic softmax weights
__device__ int   g_is64;                        // edge_index dtype flag

// ---------------- helpers ----------------
__device__ __forceinline__ void red_add_v4(float* addr, float4 v) {
    asm volatile("red.global.add.v4.f32 [%0], {%1,%2,%3,%4};"
                 :: "l"(addr), "f"(v.x), "f"(v.y), "f"(v.z), "f"(v.w)
                 : "memory");
}

// Load edge endpoint index `pos` from the raw edge_index buffer whose element
// width (int32 vs int64) was detected by probe_kernel.
__device__ __forceinline__ long long load_idx(const void* ei, size_t pos) {
    if (g_is64) return ((const long long*)ei)[pos];
    return (long long)((const int*)ei)[pos];
}

// ---------------- dtype probe: int64 vs int32 edge indices ----------------
__global__ void probe_kernel(const void* ei) {
    if (threadIdx.x == 0 && blockIdx.x == 0) {
        const long long* p64 = (const long long*)ei;
        int ok = 1;
#pragma unroll
        for (int i = 0; i < 16; i++) {
            long long v = p64[i];
            if (v < 0 || v >= NN) ok = 0;
        }
        g_is64 = ok;  // genuine int64 indices all lie in [0,NN)
    }
}

// ---------------- zero scratch that is accumulated into ----------------
__global__ void zero_kernel() {
    size_t i = (size_t)blockIdx.x * blockDim.x + threadIdx.x;
    size_t stride = (size_t)gridDim.x * blockDim.x;
    const size_t n_outs = (size_t)PP * NN * CC;
    for (size_t j = i; j < n_outs; j += stride) g_outs[j] = 0.f;
    const size_t n_den = (size_t)PP * NN * HH;
    for (size_t j = i; j < n_den; j += stride) g_denom[j] = 0.f;
    if (i < PP * CC) g_w[i] = 0.f;
}

// ---------------- SGEMM: C[M,128] = A[M,K] @ B[K,128] + bias ----------------
// mode 0: A = Aext (x_movie), C = g_h      (M=NN,   K=FIN)
// mode 1: A = g_outs,        C = g_tmp     (M=PP*NN, K=CC)
__global__ __launch_bounds__(256) void sgemm_kernel(
    const float* __restrict__ Aext, const float* __restrict__ B,
    const float* __restrict__ bias, int mode, int M, int K)
{
    const float* __restrict__ A = (mode == 0) ? Aext : g_outs;
    float* __restrict__ Cout    = (mode == 0) ? g_h  : g_tmp;

    const int BM = 128, BK = 16;
    __shared__ float As[BK][BM];
    __shared__ float Bs[BK][128];

    int tid = threadIdx.x;
    int tx = tid & 15;        // column group (8 cols each)
    int ty = tid >> 4;        // row group (8 rows each)
    int row0 = blockIdx.y * BM;

    float acc[8][8];
#pragma unroll
    for (int i = 0; i < 8; i++)
#pragma unroll
        for (int j = 0; j < 8; j++) acc[i][j] = 0.f;

    for (int k0 = 0; k0 < K; k0 += BK) {
        // load A tile (BM x BK) transposed into As
#pragma unroll
        for (int it = 0; it < 2; it++) {
            int idx = tid + it * 256;        // float4 index, 0..511
            int ar  = idx >> 2;              // 0..127
            int ac4 = idx & 3;               // 0..3
            float4 v = make_float4(0.f, 0.f, 0.f, 0.f);
            int gr = row0 + ar;
            if (gr < M)
                v = *(const float4*)&A[(size_t)gr * K + k0 + ac4 * 4];
            As[ac4 * 4 + 0][ar] = v.x;
            As[ac4 * 4 + 1][ar] = v.y;
            As[ac4 * 4 + 2][ar] = v.z;
            As[ac4 * 4 + 3][ar] = v.w;
        }
        // load B tile (BK x 128)
#pragma unroll
        for (int it = 0; it < 2; it++) {
            int idx = tid + it * 256;
            int br = idx >> 5;               // 0..15
            int bc = (idx & 31) * 4;         // 0..124
            *(float4*)&Bs[br][bc] = *(const float4*)&B[(size_t)(k0 + br) * 128 + bc];
        }
        __syncthreads();

#pragma unroll
        for (int kk = 0; kk < BK; kk++) {
            float ra[8], rb[8];
            *(float4*)&ra[0] = *(float4*)&As[kk][ty * 8];
            *(float4*)&ra[4] = *(float4*)&As[kk][ty * 8 + 4];
            *(float4*)&rb[0] = *(float4*)&Bs[kk][tx * 8];
            *(float4*)&rb[4] = *(float4*)&Bs[kk][tx * 8 + 4];
#pragma unroll
            for (int i = 0; i < 8; i++)
#pragma unroll
                for (int j = 0; j < 8; j++)
                    acc[i][j] += ra[i] * rb[j];
        }
        __syncthreads();
    }

    // epilogue: add bias, store
#pragma unroll
    for (int i = 0; i < 8; i++) {
        int gr = row0 + ty * 8 + i;
        if (gr < M) {
#pragma unroll
            for (int j = 0; j < 8; j += 4) {
                int gc = tx * 8 + j;
                float4 v;
                v.x = acc[i][j + 0] + bias[gc + 0];
                v.y = acc[i][j + 1] + bias[gc + 1];
                v.z = acc[i][j + 2] + bias[gc + 2];
                v.w = acc[i][j + 3] + bias[gc + 3];
                *(float4*)&Cout[(size_t)gr * 128 + gc] = v;
            }
        }
    }
}

// ---------------- per-node attention logits: al_s, al_d ----------------
__global__ void alsd_kernel(const float* __restrict__ asrc,
                            const float* __restrict__ adst)
{
    int i = blockIdx.x * blockDim.x + threadIdx.x;  // node*H + h
    if (i >= NN * HH) return;
    int n = i >> 3;
    int h = i & 7;
    const float4* hp = (const float4*)&g_h[(size_t)n * CC + h * DD];
    const float4* as = (const float4*)&asrc[h * DD];
    const float4* ad = (const float4*)&adst[h * DD];
    float s = 0.f, d = 0.f;
#pragma unroll
    for (int j = 0; j < 4; j++) {
        float4 hv = hp[j], av = as[j], dv = ad[j];
        s += hv.x * av.x + hv.y * av.y + hv.z * av.z + hv.w * av.w;
        d += hv.x * dv.x + hv.y * dv.y + hv.z * dv.z + hv.w * dv.w;
    }
    g_als[i] = s;
    g_ald[i] = d;
}

// ---------------- edge pass B: p=exp(leakyrelu(...)), denom += p ----------------
__global__ void edgeB_kernel(const void* __restrict__ ei, int p)
{
    int e = blockIdx.x * blockDim.x + threadIdx.x;
    if (e >= EE) return;
    long long s = load_idx(ei, (size_t)(2 * p) * EE + e);
    long long d = load_idx(ei, (size_t)(2 * p + 1) * EE + e);
    float4 s0 = *(const float4*)&g_als[s * 8];
    float4 s1 = *(const float4*)&g_als[s * 8 + 4];
    float4 d0 = *(const float4*)&g_ald[d * 8];
    float4 d1 = *(const float4*)&g_ald[d * 8 + 4];
    float ev[8];
    ev[0] = s0.x + d0.x; ev[1] = s0.y + d0.y; ev[2] = s0.z + d0.z; ev[3] = s0.w + d0.w;
    ev[4] = s1.x + d1.x; ev[5] = s1.y + d1.y; ev[6] = s1.z + d1.z; ev[7] = s1.w + d1.w;
#pragma unroll
    for (int h = 0; h < 8; h++) {
        float x = ev[h];
        x = (x > 0.f) ? x : NEG * x;
        ev[h] = expf(x);   // no max-shift needed: x bounded, exp(x) <= ~3e3
    }
    *(float4*)&g_p[(size_t)e * 8]     = make_float4(ev[0], ev[1], ev[2], ev[3]);
    *(float4*)&g_p[(size_t)e * 8 + 4] = make_float4(ev[4], ev[5], ev[6], ev[7]);
    float* den = &g_denom[(size_t)p * NN * HH + d * 8];
    red_add_v4(den,     make_float4(ev[0], ev[1], ev[2], ev[3]));
    red_add_v4(den + 4, make_float4(ev[4], ev[5], ev[6], ev[7]));
}

// ---------------- edge pass C: out[dst] += h[src] * alpha (warp per edge) ----------------
__global__ void edgeC_kernel(const void* __restrict__ ei, int p)
{
    int gid = blockIdx.x * blockDim.x + threadIdx.x;
    int e = gid >> 5;
    if (e >= EE) return;
    int l = gid & 31;
    long long s = load_idx(ei, (size_t)(2 * p) * EE + e);
    long long d = load_idx(ei, (size_t)(2 * p + 1) * EE + e);
    int head = l >> 2;
    float pv  = g_p[(size_t)e * 8 + head];
    float den = g_denom[(size_t)p * NN * HH + d * 8 + head];
    float alpha = pv / (den + 1e-16f);
    float4 hv = *(const float4*)&g_h[(size_t)s * CC + l * 4];
    float4 m  = make_float4(hv.x * alpha, hv.y * alpha, hv.z * alpha, hv.w * alpha);
    red_add_v4(&g_outs[((size_t)p * NN + d) * CC + l * 4], m);
}

// ---------------- relu in place on g_outs ----------------
__global__ void relu_kernel() {
    size_t i = (size_t)blockIdx.x * blockDim.x + threadIdx.x;
    size_t n4 = (size_t)PP * NN * CC / 4;
    size_t stride = (size_t)gridDim.x * blockDim.x;
    float4* ptr = (float4*)g_outs;
    for (size_t j = i; j < n4; j += stride) {
        float4 v = ptr[j];
        v.x = fmaxf(v.x, 0.f); v.y = fmaxf(v.y, 0.f);
        v.z = fmaxf(v.z, 0.f); v.w = fmaxf(v.w, 0.f);
        ptr[j] = v;
    }
}

// ---------------- tanh + column-mean accumulation ----------------
#define ROWS_PER_BLK 250
__global__ void tanh_mean_kernel() {
    int p = blockIdx.x;             // 0..2
    int chunk = blockIdx.y;         // 0..399
    int c = threadIdx.x;            // 0..127
    int n0 = chunk * ROWS_PER_BLK;
    float acc = 0.f;
    const float* base = &g_tmp[((size_t)p * NN + n0) * CC + c];
    for (int n = 0; n < ROWS_PER_BLK; n++)
        acc += tanhf(base[(size_t)n * CC]);
    atomicAdd(&g_w[p * CC + c], acc);
}

// ---------------- semantic softmax beta ----------------
__global__ void beta_kernel(const float* __restrict__ q) {
    __shared__ float red[128];
    __shared__ float sc[PP];
    int c = threadIdx.x;
    for (int p = 0; p < PP; p++) {
        red[c] = q[c] * g_w[p * CC + c];
        __syncthreads();
        for (int s = 64; s > 0; s >>= 1) {
            if (c < s) red[c] += red[c + s];
            __syncthreads();
        }
        if (c == 0) sc[p] = red[0] / (float)NN;
        __syncthreads();
    }
    if (c == 0) {
        float m = fmaxf(sc[0], fmaxf(sc[1], sc[2]));
        float e0 = expf(sc[0] - m), e1 = expf(sc[1] - m), e2 = expf(sc[2] - m);
        float s = e0 + e1 + e2;
        g_beta[0] = e0 / s; g_beta[1] = e1 / s; g_beta[2] = e2 / s;
    }
}

// ---------------- fused sum + final linear ----------------
__global__ void final_kernel(const float* __restrict__ linW,
                             const float* __restrict__ linb,
                             float* __restrict__ out)
{
    __shared__ float sW[CC * OUTC];
    __shared__ float sb[OUTC];
    __shared__ float sbeta[PP];
    int t = threadIdx.x;
    for (int i = t; i < CC * OUTC; i += blockDim.x) sW[i] = linW[i];
    if (t < OUTC) sb[t] = linb[t];
    if (t < PP)   sbeta[t] = g_beta[t];
    __syncthreads();
    int n = blockIdx.x * blockDim.x + t;
    if (n >= NN) return;
    float b0 = sbeta[0], b1 = sbeta[1], b2 = sbeta[2];
    const float4* o0 = (const float4*)&g_outs[(size_t)n * CC];
    const float4* o1 = (const float4*)&g_outs[((size_t)NN + n) * CC];
    const float4* o2 = (const float4*)&g_outs[((size_t)2 * NN + n) * CC];
    float a0 = sb[0], a1 = sb[1], a2 = sb[2];
#pragma unroll 8
    for (int c4 = 0; c4 < 32; c4++) {
        float4 v0 = o0[c4], v1 = o1[c4], v2 = o2[c4];
        float f[4];
        f[0] = b0 * v0.x + b1 * v1.x + b2 * v2.x;
        f[1] = b0 * v0.y + b1 * v1.y + b2 * v2.y;
        f[2] = b0 * v0.z + b1 * v1.z + b2 * v2.z;
        f[3] = b0 * v0.w + b1 * v1.w + b2 * v2.w;
        int cb = c4 * 4;
#pragma unroll
        for (int j = 0; j < 4; j++) {
            a0 += f[j] * sW[(cb + j) * 3 + 0];
            a1 += f[j] * sW[(cb + j) * 3 + 1];
            a2 += f[j] * sW[(cb + j) * 3 + 2];
        }
    }
    out[n * 3 + 0] = a0;
    out[n * 3 + 1] = a1;
    out[n * 3 + 2] = a2;
}

// ---------------- launch ----------------
extern "C" void kernel_launch(void* const* d_in, const int* in_sizes, int n_in,
                              void* d_out, int out_size)
{
    const float* x      = (const float*)d_in[0];
    const void*  ei     = (const void*)d_in[1];   // [P,2,E] int32 or int64
    const float* W_proj = (const float*)d_in[2];
    const float* b_proj = (const float*)d_in[3];
    const float* a_src  = (const float*)d_in[4];  // [P,H,D]
    const float* a_dst  = (const float*)d_in[5];
    const float* k_W    = (const float*)d_in[6];
    const float* k_b    = (const float*)d_in[7];
    const float* q      = (const float*)d_in[8];
    const float* lin_W  = (const float*)d_in[9];
    const float* lin_b  = (const float*)d_in[10];
    float*       out    = (float*)d_out;

    probe_kernel<<<1, 32>>>(ei);

    // zero accumulators
    zero_kernel<<<2048, 256>>>();

    // projection: g_h = x @ W_proj + b_proj
    sgemm_kernel<<<dim3(1, (NN + 127) / 128), 256>>>(x, W_proj, b_proj, 0, NN, FIN);

    // per-metapath GAT
    for (int p = 0; p < PP; p++) {
        alsd_kernel<<<(NN * HH + 255) / 256, 256>>>(a_src + p * HH * DD,
                                                    a_dst + p * HH * DD);
        edgeB_kernel<<<(EE + 255) / 256, 256>>>(ei, p);
        edgeC_kernel<<<(EE * 32 + 255) / 256, 256>>>(ei, p);
    }

    relu_kernel<<<4096, 256>>>();

    // semantic attention: g_tmp = g_outs @ k_W + k_b  (M = P*N)
    sgemm_kernel<<<dim3(1, (PP * NN + 127) / 128), 256>>>(nullptr, k_W, k_b, 1,
                                                          PP * NN, CC);
    tanh_mean_kernel<<<dim3(PP, NN / ROWS_PER_BLK), 128>>>();
    beta_kernel<<<1, 128>>>(q);

    // fused sum + final linear
    final_kernel<<<(NN + 255) / 256, 256>>>(lin_W, lin_b, out);
}

// round 3
// speedup vs baseline: 1.5673x; 1.5673x over previous
#include <cuda_runtime.h>
#include <cuda_bf16.h>
#include <cstdint>

#define NN   100000
#define FIN  1024
#define HH   8
#define DD   16
#define CC   128
#define EE   600000
#define PP   3
#define OUTC 3
#define NEG  0.2f

#define KSA  40    // A smem k-stride (bf16 elems), padded for conflict-free frag loads
#define NSB  136   // B smem n-stride (bf16 elems), padded for conflict-free ldmatrix

// ---------------- scratch (static device globals; no allocs) ----------------
__device__ float g_h[(size_t)NN * CC];          // projected features [N,C]
__device__ float g_outs[(size_t)PP * NN * CC];  // per-metapath GAT outputs (pre-relu)
__device__ float g_p[(size_t)EE * HH];          // per-edge exp(e) values
__device__ float g_als[(size_t)NN * HH];        // alpha_src logits per node
__device__ float g_ald[(size_t)NN * HH];        // alpha_dst logits per node
__device__ float g_denom[(size_t)PP * NN * HH]; // softmax denominators
__device__ float g_w[PP * CC];                  // semantic attn accumulators
__device__ float g_beta[PP];                    // semantic softmax weights
__device__ int   g_is64;                        // edge_index dtype flag

// ---------------- helpers ----------------
__device__ __forceinline__ void red_add_v4(float* addr, float4 v) {
    asm volatile("red.global.add.v4.f32 [%0], {%1,%2,%3,%4};"
                 :: "l"(addr), "f"(v.x), "f"(v.y), "f"(v.z), "f"(v.w)
                 : "memory");
}

__device__ __forceinline__ long long load_idx(const void* ei, size_t pos) {
    if (g_is64) return ((const long long*)ei)[pos];
    return (long long)((const int*)ei)[pos];
}

// split two fp32 into packed bf16 hi and bf16 lo (residual) pairs
__device__ __forceinline__ void split2(float v0, float v1, uint32_t& hi, uint32_t& lo) {
    __nv_bfloat16 h0 = __float2bfloat16_rn(v0);
    __nv_bfloat16 h1 = __float2bfloat16_rn(v1);
    __nv_bfloat16 l0 = __float2bfloat16_rn(v0 - __bfloat162float(h0));
    __nv_bfloat16 l1 = __float2bfloat16_rn(v1 - __bfloat162float(h1));
    hi = ((uint32_t)(*(uint16_t*)&h1) << 16) | (uint32_t)(*(uint16_t*)&h0);
    lo = ((uint32_t)(*(uint16_t*)&l1) << 16) | (uint32_t)(*(uint16_t*)&l0);
}

__device__ __forceinline__ void mma16816(float* c, const uint32_t* a, const uint32_t* b) {
    asm volatile(
        "mma.sync.aligned.m16n8k16.row.col.f32.bf16.bf16.f32 "
        "{%0,%1,%2,%3}, {%4,%5,%6,%7}, {%8,%9}, {%0,%1,%2,%3};"
        : "+f"(c[0]), "+f"(c[1]), "+f"(c[2]), "+f"(c[3])
        : "r"(a[0]), "r"(a[1]), "r"(a[2]), "r"(a[3]), "r"(b[0]), "r"(b[1]));
}

__device__ __forceinline__ void ldm_x2_t(uint32_t& r0, uint32_t& r1, uint32_t saddr) {
    asm volatile("ldmatrix.sync.aligned.m8n8.x2.trans.shared.b16 {%0,%1}, [%2];"
                 : "=r"(r0), "=r"(r1) : "r"(saddr));
}

// ---------------- dtype probe: int64 vs int32 edge indices ----------------
__global__ void probe_kernel(const void* ei) {
    if (threadIdx.x == 0 && blockIdx.x == 0) {
        const long long* p64 = (const long long*)ei;
        int ok = 1;
#pragma unroll
        for (int i = 0; i < 16; i++) {
            long long v = p64[i];
            if (v < 0 || v >= NN) ok = 0;
        }
        g_is64 = ok;
    }
}

// ---------------- zero scratch that is accumulated into ----------------
__global__ void zero_kernel() {
    size_t i = (size_t)blockIdx.x * blockDim.x + threadIdx.x;
    size_t stride = (size_t)gridDim.x * blockDim.x;
    const size_t n_outs = (size_t)PP * NN * CC;
    for (size_t j = i; j < n_outs; j += stride) g_outs[j] = 0.f;
    const size_t n_den = (size_t)PP * NN * HH;
    for (size_t j = i; j < n_den; j += stride) g_denom[j] = 0.f;
    if (i < PP * CC) g_w[i] = 0.f;
}

// ---------------- tensor-core GEMM: C[M,128] = A[M,K] @ B[K,128] + bias ----
// bf16 2-term split (hi+lo), 3 MMAs per tile: hi*hi + hi*lo + lo*hi, fp32 acc.
// MODE 0: A = Aext (x_movie), writes C = g_h.
// MODE 1: A = relu(g_outs); no C store — epilogue computes per-column sums of
//         tanh(C + bias) and accumulates them into g_w[p*CC + col].
template <int MODE>
__global__ __launch_bounds__(256) void gemm_bf16(
    const float* __restrict__ Aext, const float* __restrict__ Bw,
    const float* __restrict__ bias, int M, int K)
{
    const float* __restrict__ A = (MODE == 0) ? Aext : g_outs;

    __shared__ __align__(16) uint16_t AsH[128 * KSA];
    __shared__ __align__(16) uint16_t AsL[128 * KSA];
    __shared__ __align__(16) uint16_t BsH[32 * NSB];
    __shared__ __align__(16) uint16_t BsL[32 * NSB];
    __shared__ float colsum[128];

    int tid  = threadIdx.x;
    int lane = tid & 31;
    int warp = tid >> 5;
    int wm = warp & 3;          // 4 warps over M (32 rows each)
    int wn = warp >> 2;         // 2 warps over N (64 cols each)
    int g  = lane >> 2;
    int t  = lane & 3;
    int row0 = blockIdx.x * 128;

    float acc[2][8][4];
#pragma unroll
    for (int mt = 0; mt < 2; mt++)
#pragma unroll
        for (int nt = 0; nt < 8; nt++)
#pragma unroll
            for (int j = 0; j < 4; j++) acc[mt][nt][j] = 0.f;

    for (int k0 = 0; k0 < K; k0 += 32) {
        // ---- load + split A tile (128 x 32) ----
#pragma unroll
        for (int it = 0; it < 4; it++) {
            int m  = (tid >> 3) + it * 32;
            int k4 = (tid & 7) * 4;
            int gr = row0 + m;
            float4 v = make_float4(0.f, 0.f, 0.f, 0.f);
            if (gr < M) v = *(const float4*)&A[(size_t)gr * K + k0 + k4];
            if (MODE == 1) {
                v.x = fmaxf(v.x, 0.f); v.y = fmaxf(v.y, 0.f);
                v.z = fmaxf(v.z, 0.f); v.w = fmaxf(v.w, 0.f);
            }
            uint32_t h01, l01, h23, l23;
            split2(v.x, v.y, h01, l01);
            split2(v.z, v.w, h23, l23);
            *(uint32_t*)&AsH[m * KSA + k4]     = h01;
            *(uint32_t*)&AsH[m * KSA + k4 + 2] = h23;
            *(uint32_t*)&AsL[m * KSA + k4]     = l01;
            *(uint32_t*)&AsL[m * KSA + k4 + 2] = l23;
        }
        // ---- load + split B tile (32 x 128), k-major ----
#pragma unroll
        for (int it = 0; it < 4; it++) {
            int kk = (tid >> 5) + it * 8;
            int n4 = (tid & 31) * 4;
            float4 v = *(const float4*)&Bw[(size_t)(k0 + kk) * 128 + n4];
            uint32_t h01, l01, h23, l23;
            split2(v.x, v.y, h01, l01);
            split2(v.z, v.w, h23, l23);
            *(uint32_t*)&BsH[kk * NSB + n4]     = h01;
            *(uint32_t*)&BsH[kk * NSB + n4 + 2] = h23;
            *(uint32_t*)&BsL[kk * NSB + n4]     = l01;
            *(uint32_t*)&BsL[kk * NSB + n4 + 2] = l23;
        }
        __syncthreads();

#pragma unroll
        for (int ks = 0; ks < 32; ks += 16) {
            uint32_t ah[2][4], al[2][4];
#pragma unroll
            for (int mt = 0; mt < 2; mt++) {
                int r = wm * 32 + mt * 16 + g;
                const uint16_t* pH = &AsH[r * KSA + ks + 2 * t];
                const uint16_t* pL = &AsL[r * KSA + ks + 2 * t];
                ah[mt][0] = *(const uint32_t*)pH;
                ah[mt][1] = *(const uint32_t*)(pH + 8 * KSA);
                ah[mt][2] = *(const uint32_t*)(pH + 8);
                ah[mt][3] = *(const uint32_t*)(pH + 8 * KSA + 8);
                al[mt][0] = *(const uint32_t*)pL;
                al[mt][1] = *(const uint32_t*)(pL + 8 * KSA);
                al[mt][2] = *(const uint32_t*)(pL + 8);
                al[mt][3] = *(const uint32_t*)(pL + 8 * KSA + 8);
            }
#pragma unroll
            for (int nt = 0; nt < 8; nt++) {
                int nb = wn * 64 + nt * 8;
                uint32_t bh[2], bl[2];
                uint32_t srcH = (uint32_t)__cvta_generic_to_shared(
                    &BsH[(ks + (lane & 15)) * NSB + nb]);
                uint32_t srcL = (uint32_t)__cvta_generic_to_shared(
                    &BsL[(ks + (lane & 15)) * NSB + nb]);
                ldm_x2_t(bh[0], bh[1], srcH);
                ldm_x2_t(bl[0], bl[1], srcL);
#pragma unroll
                for (int mt = 0; mt < 2; mt++) {
                    mma16816(acc[mt][nt], ah[mt], bh);
                    mma16816(acc[mt][nt], ah[mt], bl);
                    mma16816(acc[mt][nt], al[mt], bh);
                }
            }
        }
        __syncthreads();
    }

    if (MODE == 0) {
        // write C = acc + bias
#pragma unroll
        for (int mt = 0; mt < 2; mt++) {
            int r0 = row0 + wm * 32 + mt * 16 + g;
#pragma unroll
            for (int nt = 0; nt < 8; nt++) {
                int c = wn * 64 + nt * 8 + 2 * t;
                float b0 = bias[c], b1 = bias[c + 1];
                if (r0 < M) {
                    float2 s = make_float2(acc[mt][nt][0] + b0, acc[mt][nt][1] + b1);
                    *(float2*)&g_h[(size_t)r0 * 128 + c] = s;
                }
                int r1 = r0 + 8;
                if (r1 < M) {
                    float2 s = make_float2(acc[mt][nt][2] + b0, acc[mt][nt][3] + b1);
                    *(float2*)&g_h[(size_t)r1 * 128 + c] = s;
                }
            }
        }
    } else {
        // epilogue: colwise sum of tanh(C + bias) into g_w[p*CC + col]
        bool crossing = (row0 / NN) != ((row0 + 127) / NN);
        if (!crossing) {
            int p = row0 / NN;
            float cs[8][2];
#pragma unroll
            for (int nt = 0; nt < 8; nt++) { cs[nt][0] = 0.f; cs[nt][1] = 0.f; }
#pragma unroll
            for (int mt = 0; mt < 2; mt++) {
                int r0 = row0 + wm * 32 + mt * 16 + g;
                int r1 = r0 + 8;
#pragma unroll
                for (int nt = 0; nt < 8; nt++) {
                    int c = wn * 64 + nt * 8 + 2 * t;
                    float b0 = bias[c], b1 = bias[c + 1];
                    if (r0 < M) {
                        cs[nt][0] += tanhf(acc[mt][nt][0] + b0);
                        cs[nt][1] += tanhf(acc[mt][nt][1] + b1);
                    }
                    if (r1 < M) {
                        cs[nt][0] += tanhf(acc[mt][nt][2] + b0);
                        cs[nt][1] += tanhf(acc[mt][nt][3] + b1);
                    }
                }
            }
            // butterfly over the g-lanes (lanes differing in bits 2..4)
#pragma unroll
            for (int nt = 0; nt < 8; nt++) {
#pragma unroll
                for (int m = 4; m <= 16; m <<= 1) {
                    cs[nt][0] += __shfl_xor_sync(0xffffffffu, cs[nt][0], m);
                    cs[nt][1] += __shfl_xor_sync(0xffffffffu, cs[nt][1], m);
                }
            }
            if (tid < 128) colsum[tid] = 0.f;
            __syncthreads();
            if (g == 0) {
#pragma unroll
                for (int nt = 0; nt < 8; nt++) {
                    int c = wn * 64 + nt * 8 + 2 * t;
                    atomicAdd(&colsum[c], cs[nt][0]);
                    atomicAdd(&colsum[c + 1], cs[nt][1]);
                }
            }
            __syncthreads();
            if (tid < 128) atomicAdd(&g_w[p * CC + tid], colsum[tid]);
        } else {
            // rare blocks straddling a metapath boundary: direct atomics
#pragma unroll
            for (int mt = 0; mt < 2; mt++) {
                int r0 = row0 + wm * 32 + mt * 16 + g;
                int r1 = r0 + 8;
#pragma unroll
                for (int nt = 0; nt < 8; nt++) {
                    int c = wn * 64 + nt * 8 + 2 * t;
                    float b0 = bias[c], b1 = bias[c + 1];
                    if (r0 < M) {
                        atomicAdd(&g_w[(r0 / NN) * CC + c],     tanhf(acc[mt][nt][0] + b0));
                        atomicAdd(&g_w[(r0 / NN) * CC + c + 1], tanhf(acc[mt][nt][1] + b1));
                    }
                    if (r1 < M) {
                        atomicAdd(&g_w[(r1 / NN) * CC + c],     tanhf(acc[mt][nt][2] + b0));
                        atomicAdd(&g_w[(r1 / NN) * CC + c + 1], tanhf(acc[mt][nt][3] + b1));
                    }
                }
            }
        }
    }
}

// ---------------- per-node attention logits: al_s, al_d ----------------
__global__ void alsd_kernel(const float* __restrict__ asrc,
                            const float* __restrict__ adst)
{
    int i = blockIdx.x * blockDim.x + threadIdx.x;  // node*H + h
    if (i >= NN * HH) return;
    int n = i >> 3;
    int h = i & 7;
    const float4* hp = (const float4*)&g_h[(size_t)n * CC + h * DD];
    const float4* as = (const float4*)&asrc[h * DD];
    const float4* ad = (const float4*)&adst[h * DD];
    float s = 0.f, d = 0.f;
#pragma unroll
    for (int j = 0; j < 4; j++) {
        float4 hv = hp[j], av = as[j], dv = ad[j];
        s += hv.x * av.x + hv.y * av.y + hv.z * av.z + hv.w * av.w;
        d += hv.x * dv.x + hv.y * dv.y + hv.z * dv.z + hv.w * dv.w;
    }
    g_als[i] = s;
    g_ald[i] = d;
}

// ---------------- edge pass B: p=exp(leakyrelu(...)), denom += p ----------------
__global__ void edgeB_kernel(const void* __restrict__ ei, int p)
{
    int e = blockIdx.x * blockDim.x + threadIdx.x;
    if (e >= EE) return;
    long long s = load_idx(ei, (size_t)(2 * p) * EE + e);
    long long d = load_idx(ei, (size_t)(2 * p + 1) * EE + e);
    float4 s0 = *(const float4*)&g_als[s * 8];
    float4 s1 = *(const float4*)&g_als[s * 8 + 4];
    float4 d0 = *(const float4*)&g_ald[d * 8];
    float4 d1 = *(const float4*)&g_ald[d * 8 + 4];
    float ev[8];
    ev[0] = s0.x + d0.x; ev[1] = s0.y + d0.y; ev[2] = s0.z + d0.z; ev[3] = s0.w + d0.w;
    ev[4] = s1.x + d1.x; ev[5] = s1.y + d1.y; ev[6] = s1.z + d1.z; ev[7] = s1.w + d1.w;
#pragma unroll
    for (int h = 0; h < 8; h++) {
        float x = ev[h];
        x = (x > 0.f) ? x : NEG * x;
        ev[h] = expf(x);   // logits bounded; no max-shift needed in fp32
    }
    *(float4*)&g_p[(size_t)e * 8]     = make_float4(ev[0], ev[1], ev[2], ev[3]);
    *(float4*)&g_p[(size_t)e * 8 + 4] = make_float4(ev[4], ev[5], ev[6], ev[7]);
    float* den = &g_denom[(size_t)p * NN * HH + d * 8];
    red_add_v4(den,     make_float4(ev[0], ev[1], ev[2], ev[3]));
    red_add_v4(den + 4, make_float4(ev[4], ev[5], ev[6], ev[7]));
}

// ---------------- edge pass C: out[dst] += h[src] * alpha (warp per edge) ----------------
__global__ void edgeC_kernel(const void* __restrict__ ei, int p)
{
    int gid = blockIdx.x * blockDim.x + threadIdx.x;
    int e = gid >> 5;
    if (e >= EE) return;
    int l = gid & 31;
    long long s = load_idx(ei, (size_t)(2 * p) * EE + e);
    long long d = load_idx(ei, (size_t)(2 * p + 1) * EE + e);
    int head = l >> 2;
    float pv  = g_p[(size_t)e * 8 + head];
    float den = g_denom[(size_t)p * NN * HH + d * 8 + head];
    float alpha = pv / (den + 1e-16f);
    float4 hv = *(const float4*)&g_h[(size_t)s * CC + l * 4];
    float4 m  = make_float4(hv.x * alpha, hv.y * alpha, hv.z * alpha, hv.w * alpha);
    red_add_v4(&g_outs[((size_t)p * NN + d) * CC + l * 4], m);
}

// ---------------- semantic softmax beta ----------------
__global__ void beta_kernel(const float* __restrict__ q) {
    __shared__ float red[128];
    __shared__ float sc[PP];
    int c = threadIdx.x;
    for (int p = 0; p < PP; p++) {
        red[c] = q[c] * g_w[p * CC + c];
        __syncthreads();
        for (int s = 64; s > 0; s >>= 1) {
            if (c < s) red[c] += red[c + s];
            __syncthreads();
        }
        if (c == 0) sc[p] = red[0] / (float)NN;
        __syncthreads();
    }
    if (c == 0) {
        float m = fmaxf(sc[0], fmaxf(sc[1], sc[2]));
        float e0 = expf(sc[0] - m), e1 = expf(sc[1] - m), e2 = expf(sc[2] - m);
        float s = e0 + e1 + e2;
        g_beta[0] = e0 / s; g_beta[1] = e1 / s; g_beta[2] = e2 / s;
    }
}

// ---------------- fused relu + weighted sum + final linear ----------------
__global__ void final_kernel(const float* __restrict__ linW,
                             const float* __restrict__ linb,
                             float* __restrict__ out)
{
    __shared__ float sW[CC * OUTC];
    __shared__ float sb[OUTC];
    __shared__ float sbeta[PP];
    int t = threadIdx.x;
    for (int i = t; i < CC * OUTC; i += blockDim.x) sW[i] = linW[i];
    if (t < OUTC) sb[t] = linb[t];
    if (t < PP)   sbeta[t] = g_beta[t];
    __syncthreads();
    int n = blockIdx.x * blockDim.x + t;
    if (n >= NN) return;
    float b0 = sbeta[0], b1 = sbeta[1], b2 = sbeta[2];
    const float4* o0 = (const float4*)&g_outs[(size_t)n * CC];
    const float4* o1 = (const float4*)&g_outs[((size_t)NN + n) * CC];
    const float4* o2 = (const float4*)&g_outs[((size_t)2 * NN + n) * CC];
    float a0 = sb[0], a1 = sb[1], a2 = sb[2];
#pragma unroll 8
    for (int c4 = 0; c4 < 32; c4++) {
        float4 v0 = o0[c4], v1 = o1[c4], v2 = o2[c4];
        float f[4];
        f[0] = b0 * fmaxf(v0.x, 0.f) + b1 * fmaxf(v1.x, 0.f) + b2 * fmaxf(v2.x, 0.f);
        f[1] = b0 * fmaxf(v0.y, 0.f) + b1 * fmaxf(v1.y, 0.f) + b2 * fmaxf(v2.y, 0.f);
        f[2] = b0 * fmaxf(v0.z, 0.f) + b1 * fmaxf(v1.z, 0.f) + b2 * fmaxf(v2.z, 0.f);
        f[3] = b0 * fmaxf(v0.w, 0.f) + b1 * fmaxf(v1.w, 0.f) + b2 * fmaxf(v2.w, 0.f);
        int cb = c4 * 4;
#pragma unroll
        for (int j = 0; j < 4; j++) {
            a0 += f[j] * sW[(cb + j) * 3 + 0];
            a1 += f[j] * sW[(cb + j) * 3 + 1];
            a2 += f[j] * sW[(cb + j) * 3 + 2];
        }
    }
    out[n * 3 + 0] = a0;
    out[n * 3 + 1] = a1;
    out[n * 3 + 2] = a2;
}

// ---------------- launch ----------------
extern "C" void kernel_launch(void* const* d_in, const int* in_sizes, int n_in,
                              void* d_out, int out_size)
{
    const float* x      = (const float*)d_in[0];
    const void*  ei     = (const void*)d_in[1];   // [P,2,E] int32 or int64
    const float* W_proj = (const float*)d_in[2];
    const float* b_proj = (const float*)d_in[3];
    const float* a_src  = (const float*)d_in[4];  // [P,H,D]
    const float* a_dst  = (const float*)d_in[5];
    const float* k_W    = (const float*)d_in[6];
    const float* k_b    = (const float*)d_in[7];
    const float* q      = (const float*)d_in[8];
    const float* lin_W  = (const float*)d_in[9];
    const float* lin_b  = (const float*)d_in[10];
    float*       out    = (float*)d_out;

    probe_kernel<<<1, 32>>>(ei);
    zero_kernel<<<2048, 256>>>();

    // projection: g_h = x @ W_proj + b_proj (tensor cores, bf16-split)
    gemm_bf16<0><<<(NN + 127) / 128, 256>>>(x, W_proj, b_proj, NN, FIN);

    // per-metapath GAT
    for (int p = 0; p < PP; p++) {
        alsd_kernel<<<(NN * HH + 255) / 256, 256>>>(a_src + p * HH * DD,
                                                    a_dst + p * HH * DD);
        edgeB_kernel<<<(EE + 255) / 256, 256>>>(ei, p);
        edgeC_kernel<<<(EE * 32 + 255) / 256, 256>>>(ei, p);
    }

    // semantic attention: fused relu + GEMM + tanh + column-mean into g_w
    gemm_bf16<1><<<(PP * NN + 127) / 128, 256>>>(nullptr, k_W, k_b, PP * NN, CC);
    beta_kernel<<<1, 128>>>(q);

    // fused relu + weighted sum + final linear
    final_kernel<<<(NN + 255) / 256, 256>>>(lin_W, lin_b, out);
}